// round 2
// baseline (speedup 1.0000x reference)
#include <cuda_runtime.h>
#include <math.h>

#define B_   128
#define D_   20
#define W_   8
#define HW   64
#define E_   4
#define HID  4096
#define IN_  64

// ---------------- device scratch (no allocations allowed) ----------------
__device__ float g_flat[B_ * IN_];
__device__ int   g_sel[B_];
__device__ int   g_counts[E_];
__device__ int   g_list[E_ * B_];
__device__ float g_h[(size_t)B_ * HID];
__device__ float g_lg[(size_t)B_ * HID];

// ---------------- reset ----------------
__global__ void k_reset() {
    if (threadIdx.x < E_) g_counts[threadIdx.x] = 0;
}

// ---------------- conv1 + conv2 + gating + h ----------------
// one block per sample, 256 threads
__global__ void k1_conv_gate_h(const float* __restrict__ in,
                               const float* __restrict__ c1w,
                               const float* __restrict__ c1b,
                               const float* __restrict__ c2w,
                               const float* __restrict__ c2b,
                               const float* __restrict__ wg,
                               const float* __restrict__ w1,
                               const float* __restrict__ b1) {
    const int b = blockIdx.x;
    const int t = threadIdx.x;

    __shared__ float s_in[D_ * HW];     // 1280 input (d,h,w)
    __shared__ float s_pl[D_ * HW];     // conv1 plane for one out-channel
    __shared__ float s_c1w[272];        // 10*27
    __shared__ float s_c2w[1800];       // 10*20*9
    __shared__ float s_acc[4][HW];      // conv2 partials (d split 4 ways)
    __shared__ float s_flat[IN_];
    __shared__ float s_log[E_];
    __shared__ int   s_sel;

    for (int i = t; i < D_ * HW; i += 256) s_in[i] = in[b * D_ * HW + i];
    for (int i = t; i < 270;      i += 256) s_c1w[i] = c1w[i];
    for (int i = t; i < 1800;     i += 256) s_c2w[i] = c2w[i];
    s_acc[t >> 6][t & 63] = 0.0f;
    __syncthreads();

    for (int ic = 0; ic < 10; ic++) {
        // conv1 plane for channel ic (padded 3x3x3), ReLU
        const float bias = c1b[ic];
        for (int idx = t; idx < D_ * HW; idx += 256) {
            const int d = idx >> 6, h = (idx >> 3) & 7, w = idx & 7;
            float a = bias;
            #pragma unroll
            for (int kd = 0; kd < 3; kd++) {
                const int dd = d + kd - 1;
                if ((unsigned)dd >= (unsigned)D_) continue;
                #pragma unroll
                for (int kh = 0; kh < 3; kh++) {
                    const int hh = h + kh - 1;
                    if ((unsigned)hh >= 8u) continue;
                    #pragma unroll
                    for (int kw = 0; kw < 3; kw++) {
                        const int ww = w + kw - 1;
                        if ((unsigned)ww >= 8u) continue;
                        a += s_in[dd * 64 + hh * 8 + ww] * s_c1w[ic * 27 + kd * 9 + kh * 3 + kw];
                    }
                }
            }
            s_pl[idx] = fmaxf(a, 0.0f);
        }
        __syncthreads();

        // conv2 partial: thread -> (part = d-range, hw)
        {
            const int part = t >> 6, hw = t & 63, h = hw >> 3, w = hw & 7;
            float a = 0.0f;
            for (int d = part * 5; d < part * 5 + 5; d++) {
                #pragma unroll
                for (int kh = 0; kh < 3; kh++) {
                    const int hh = h + kh - 1;
                    if ((unsigned)hh >= 8u) continue;
                    #pragma unroll
                    for (int kw = 0; kw < 3; kw++) {
                        const int ww = w + kw - 1;
                        if ((unsigned)ww >= 8u) continue;
                        a += s_pl[d * 64 + hh * 8 + ww] * s_c2w[(ic * 20 + d) * 9 + kh * 3 + kw];
                    }
                }
            }
            s_acc[part][hw] += a;
        }
        __syncthreads();
    }

    if (t < 64) {
        const float v = s_acc[0][t] + s_acc[1][t] + s_acc[2][t] + s_acc[3][t] + c2b[0];
        const float f = fmaxf(v, 0.0f);
        s_flat[t] = f;
        g_flat[b * 64 + t] = f;
    }
    __syncthreads();

    // gating logits (64 x 4)
    if (t < E_) {
        float a = 0.0f;
        for (int i = 0; i < 64; i++) a += s_flat[i] * wg[i * E_ + t];
        s_log[t] = a;
    }
    __syncthreads();
    if (t == 0) {
        int best = 0; float bv = s_log[0];
        #pragma unroll
        for (int e = 1; e < E_; e++) if (s_log[e] > bv) { bv = s_log[e]; best = e; }
        s_sel = best;
        g_sel[b] = best;
        const int pos = atomicAdd(&g_counts[best], 1);
        g_list[best * B_ + pos] = b;
    }
    __syncthreads();

    // h[b] = relu(flat @ w1[e] + b1[e])   (each thread 16 strided outputs)
    const int e = s_sel;
    float acc[16];
    #pragma unroll
    for (int u = 0; u < 16; u++) acc[u] = b1[e * HID + t + 256 * u];
    const float* w1e = w1 + (size_t)e * IN_ * HID;
    for (int i = 0; i < 64; i++) {
        const float f = s_flat[i];
        const float* row = w1e + (size_t)i * HID;
        #pragma unroll
        for (int u = 0; u < 16; u++) acc[u] += f * row[t + 256 * u];
    }
    #pragma unroll
    for (int u = 0; u < 16; u++)
        g_h[(size_t)b * HID + t + 256 * u] = fmaxf(acc[u], 0.0f);
}

// ---------------- aux loss (exact, from counts) ----------------
__global__ void k_aux(float* __restrict__ out, int out_size) {
    if (out_size <= B_ * D_ * HW) return;
    const float c0 = (float)g_counts[0], c1 = (float)g_counts[1];
    const float c2 = (float)g_counts[2], c3 = (float)g_counts[3];
    const float mean = (c0 + c1 + c2 + c3) * 0.25f;
    const float d0 = c0 - mean, d1 = c1 - mean, d2 = c2 - mean, d3 = c3 - mean;
    const float var = (d0 * d0 + d1 * d1 + d2 * d2 + d3 * d3) / 3.0f;  // ddof=1
    const float cv2 = var / (mean * mean + 1e-10f);
    out[B_ * D_ * HW] = 2.0f * cv2 * 1e-2f;  // importance == load
}

// ---------------- expert GEMM:  logits2 = h @ w2[e] + b2[e] ----------------
#define BM 32
#define BN 128
#define BK 16
__global__ void k_gemm(const float* __restrict__ w2, const float* __restrict__ b2) {
    const int nt = blockIdx.x, mc = blockIdx.y, e = blockIdx.z;
    const int ce = g_counts[e];
    if (mc * BM >= ce) return;

    __shared__ float As[BK][BM];
    __shared__ float Bs[BK][BN];
    __shared__ int   sbs[BM];

    const int t = threadIdx.x;
    if (t < BM) {
        const int m = mc * BM + t;
        sbs[t] = (m < ce) ? g_list[e * B_ + m] : -1;
    }
    __syncthreads();

    const int ty = t >> 5;      // 0..7  -> rows ty*4..+3
    const int tx = t & 31;      // 0..31 -> cols tx*4..+3
    const int lm = t >> 2, lkq = t & 3;    // A-load mapping (t<128)
    const int brow = t >> 4, bc = t & 15;  // B-load mapping

    const int   ab  = (t < 128) ? sbs[lm] : -1;
    const float* w2e = w2 + (size_t)e * HID * HID + (size_t)nt * BN;

    float acc[4][4];
    #pragma unroll
    for (int r = 0; r < 4; r++)
        #pragma unroll
        for (int c = 0; c < 4; c++) acc[r][c] = 0.0f;

    for (int k0 = 0; k0 < HID; k0 += BK) {
        if (t < 128) {
            float4 v = make_float4(0.f, 0.f, 0.f, 0.f);
            if (ab >= 0) v = *(const float4*)&g_h[(size_t)ab * HID + k0 + lkq * 4];
            As[lkq * 4 + 0][lm] = v.x;
            As[lkq * 4 + 1][lm] = v.y;
            As[lkq * 4 + 2][lm] = v.z;
            As[lkq * 4 + 3][lm] = v.w;
        }
        {
            const float* src = w2e + (size_t)(k0 + brow) * HID;
            const float4 v0 = *(const float4*)&src[bc * 4];
            const float4 v1 = *(const float4*)&src[(bc + 16) * 4];
            *(float4*)&Bs[brow][bc * 4]        = v0;
            *(float4*)&Bs[brow][(bc + 16) * 4] = v1;
        }
        __syncthreads();

        #pragma unroll
        for (int k = 0; k < BK; k++) {
            const float4 a  = *(const float4*)&As[k][ty * 4];
            const float4 bv = *(const float4*)&Bs[k][tx * 4];
            acc[0][0] += a.x * bv.x; acc[0][1] += a.x * bv.y; acc[0][2] += a.x * bv.z; acc[0][3] += a.x * bv.w;
            acc[1][0] += a.y * bv.x; acc[1][1] += a.y * bv.y; acc[1][2] += a.y * bv.z; acc[1][3] += a.y * bv.w;
            acc[2][0] += a.z * bv.x; acc[2][1] += a.z * bv.y; acc[2][2] += a.z * bv.z; acc[2][3] += a.z * bv.w;
            acc[3][0] += a.w * bv.x; acc[3][1] += a.w * bv.y; acc[3][2] += a.w * bv.z; acc[3][3] += a.w * bv.w;
        }
        __syncthreads();
    }

    #pragma unroll
    for (int r = 0; r < 4; r++) {
        const int bb = sbs[ty * 4 + r];
        if (bb >= 0) {
            const int n = nt * BN + tx * 4;
            float4 o;
            o.x = acc[r][0] + b2[e * HID + n + 0];
            o.y = acc[r][1] + b2[e * HID + n + 1];
            o.z = acc[r][2] + b2[e * HID + n + 2];
            o.w = acc[r][3] + b2[e * HID + n + 3];
            *(float4*)&g_lg[(size_t)bb * HID + n] = o;
        }
    }
}

// ---------------- softmax + per-sample transform + sigmoid ----------------
// one block per sample, 256 threads
__global__ void k_softmax_apply(const float* __restrict__ in, float* __restrict__ out) {
    const int b = blockIdx.x;
    const int t = threadIdx.x;

    __shared__ float s_l[HID];        // logits -> exp values
    __shared__ float s_y[64 * 65];    // y transposed, padded (conflict-free)
    __shared__ float s_in[D_ * 64];
    __shared__ float redm[8];
    __shared__ float reds[8];

    #pragma unroll
    for (int u = 0; u < 16; u++) s_l[t + 256 * u] = g_lg[(size_t)b * HID + t + 256 * u];
    for (int i = t; i < D_ * 64; i += 256) s_in[i] = in[b * D_ * 64 + i];
    __syncthreads();

    // row max
    float v = -1e30f;
    #pragma unroll
    for (int u = 0; u < 16; u++) v = fmaxf(v, s_l[t + 256 * u]);
    #pragma unroll
    for (int o = 16; o; o >>= 1) v = fmaxf(v, __shfl_xor_sync(0xffffffffu, v, o));
    if ((t & 31) == 0) redm[t >> 5] = v;
    __syncthreads();
    float mx = redm[0];
    #pragma unroll
    for (int i = 1; i < 8; i++) mx = fmaxf(mx, redm[i]);

    // exp + sum
    float s = 0.0f;
    #pragma unroll
    for (int u = 0; u < 16; u++) {
        const int idx = t + 256 * u;
        const float e = expf(s_l[idx] - mx);
        s_l[idx] = e;
        s += e;
    }
    #pragma unroll
    for (int o = 16; o; o >>= 1) s += __shfl_xor_sync(0xffffffffu, s, o);
    if ((t & 31) == 0) reds[t >> 5] = s;
    __syncthreads();
    float tot = 0.0f;
    #pragma unroll
    for (int i = 0; i < 8; i++) tot += reds[i];
    const float inv = 1.0f / tot;

    // normalized y stored transposed: y[i*64+j] -> s_y[j*65+i]
    #pragma unroll
    for (int u = 0; u < 16; u++) {
        const int idx = t + 256 * u;
        const int i = idx >> 6, j = idx & 63;
        s_y[j * 65 + i] = s_l[idx] * inv;
    }
    __syncthreads();

    // out[b,d,i] = sigmoid( sum_j y[i,j] * in[b,d,j] )
    for (int idx = t; idx < D_ * 64; idx += 256) {
        const int d = idx >> 6, i = idx & 63;
        float a = 0.0f;
        #pragma unroll
        for (int j = 0; j < 64; j++) a += s_y[j * 65 + i] * s_in[d * 64 + j];
        out[(b * D_ + d) * 64 + i] = 1.0f / (1.0f + expf(-a));
    }
}

// ---------------- launch ----------------
extern "C" void kernel_launch(void* const* d_in, const int* in_sizes, int n_in,
                              void* d_out, int out_size) {
    (void)in_sizes; (void)n_in;
    const float* in  = (const float*)d_in[0];
    const float* c1w = (const float*)d_in[1];
    const float* c1b = (const float*)d_in[2];
    const float* c2w = (const float*)d_in[3];
    const float* c2b = (const float*)d_in[4];
    const float* wg  = (const float*)d_in[5];
    const float* w1  = (const float*)d_in[6];
    const float* b1  = (const float*)d_in[7];
    const float* w2  = (const float*)d_in[8];
    const float* b2  = (const float*)d_in[9];
    float* out = (float*)d_out;

    k_reset<<<1, 32>>>();
    k1_conv_gate_h<<<B_, 256>>>(in, c1w, c1b, c2w, c2b, wg, w1, b1);
    k_aux<<<1, 1>>>(out, out_size);
    dim3 g3(HID / BN, B_ / BM, E_);
    k_gemm<<<g3, 256>>>(w2, b2);
    k_softmax_apply<<<B_, 256>>>(in, out);
}

// round 4
// speedup vs baseline: 1.5526x; 1.5526x over previous
#include <cuda_runtime.h>
#include <math.h>

#define B_     128
#define D_     20
#define HW     64
#define E_     4
#define HID    4096
#define IN_    64

#define SPLITK 8
#define KR     (HID / SPLITK)   // 512
#define BM     32
#define BN2    256
#define BK2    16
#define NIT    (KR / BK2)       // 32

typedef unsigned long long u64;

// ---------------- device scratch ----------------
__device__ int   g_sel[B_];
__device__ int   g_counts[E_];
__device__ int   g_list[E_ * B_];
__device__ float g_h[(size_t)B_ * HID];
__device__ float g_part[SPLITK][B_][HID];   // 16MB split-K partials

__device__ __forceinline__ void ffma2(u64 &d, u64 a, u64 b) {
    asm("fma.rn.f32x2 %0, %1, %2, %0;" : "+l"(d) : "l"(a), "l"(b));
}
__device__ __forceinline__ float2 upk(u64 v) {
    float2 r; asm("mov.b64 {%0,%1}, %2;" : "=f"(r.x), "=f"(r.y) : "l"(v)); return r;
}

// ---------------- reset ----------------
__global__ void k_reset() {
    if (threadIdx.x < E_) g_counts[threadIdx.x] = 0;
}

// ---------------- conv1 + conv2 + gating + h ----------------
__global__ void k1_conv_gate_h(const float* __restrict__ in,
                               const float* __restrict__ c1w,
                               const float* __restrict__ c1b,
                               const float* __restrict__ c2w,
                               const float* __restrict__ c2b,
                               const float* __restrict__ wg,
                               const float* __restrict__ w1,
                               const float* __restrict__ b1) {
    const int b = blockIdx.x;
    const int t = threadIdx.x;

    __shared__ float s_in[D_ * HW];
    __shared__ float s_pl[D_ * HW];
    __shared__ float s_c1w[272];
    __shared__ float s_c2w[1800];
    __shared__ float s_acc[4][HW];
    __shared__ float s_flat[IN_];
    __shared__ float s_log[E_];
    __shared__ int   s_sel;

    for (int i = t; i < D_ * HW; i += 256) s_in[i] = in[b * D_ * HW + i];
    for (int i = t; i < 270;      i += 256) s_c1w[i] = c1w[i];
    for (int i = t; i < 1800;     i += 256) s_c2w[i] = c2w[i];
    s_acc[t >> 6][t & 63] = 0.0f;
    __syncthreads();

    for (int ic = 0; ic < 10; ic++) {
        const float bias = c1b[ic];
        for (int idx = t; idx < D_ * HW; idx += 256) {
            const int d = idx >> 6, h = (idx >> 3) & 7, w = idx & 7;
            float a = bias;
            #pragma unroll
            for (int kd = 0; kd < 3; kd++) {
                const int dd = d + kd - 1;
                if ((unsigned)dd >= (unsigned)D_) continue;
                #pragma unroll
                for (int kh = 0; kh < 3; kh++) {
                    const int hh = h + kh - 1;
                    if ((unsigned)hh >= 8u) continue;
                    #pragma unroll
                    for (int kw = 0; kw < 3; kw++) {
                        const int ww = w + kw - 1;
                        if ((unsigned)ww >= 8u) continue;
                        a += s_in[dd * 64 + hh * 8 + ww] * s_c1w[ic * 27 + kd * 9 + kh * 3 + kw];
                    }
                }
            }
            s_pl[idx] = fmaxf(a, 0.0f);
        }
        __syncthreads();
        {
            const int part = t >> 6, hw = t & 63, h = hw >> 3, w = hw & 7;
            float a = 0.0f;
            for (int d = part * 5; d < part * 5 + 5; d++) {
                #pragma unroll
                for (int kh = 0; kh < 3; kh++) {
                    const int hh = h + kh - 1;
                    if ((unsigned)hh >= 8u) continue;
                    #pragma unroll
                    for (int kw = 0; kw < 3; kw++) {
                        const int ww = w + kw - 1;
                        if ((unsigned)ww >= 8u) continue;
                        a += s_pl[d * 64 + hh * 8 + ww] * s_c2w[(ic * 20 + d) * 9 + kh * 3 + kw];
                    }
                }
            }
            s_acc[part][hw] += a;
        }
        __syncthreads();
    }

    if (t < 64) {
        const float v = s_acc[0][t] + s_acc[1][t] + s_acc[2][t] + s_acc[3][t] + c2b[0];
        s_flat[t] = fmaxf(v, 0.0f);
    }
    __syncthreads();

    if (t < E_) {
        float a = 0.0f;
        for (int i = 0; i < 64; i++) a += s_flat[i] * wg[i * E_ + t];
        s_log[t] = a;
    }
    __syncthreads();
    if (t == 0) {
        int best = 0; float bv = s_log[0];
        #pragma unroll
        for (int e = 1; e < E_; e++) if (s_log[e] > bv) { bv = s_log[e]; best = e; }
        s_sel = best;
        g_sel[b] = best;
        const int pos = atomicAdd(&g_counts[best], 1);
        g_list[best * B_ + pos] = b;
    }
    __syncthreads();

    // h[b] = relu(flat @ w1[e] + b1[e]); thread t owns 16 contiguous cols t*16..
    const int e = s_sel;
    const int cb = t * 16;
    float4 acc4[4];
    #pragma unroll
    for (int j = 0; j < 4; j++) acc4[j] = *(const float4*)&b1[e * HID + cb + j * 4];
    const float* w1e = w1 + (size_t)e * IN_ * HID + cb;
    for (int i = 0; i < 64; i++) {
        const float f = s_flat[i];
        const float* row = w1e + (size_t)i * HID;
        #pragma unroll
        for (int j = 0; j < 4; j++) {
            const float4 w = *(const float4*)&row[j * 4];
            acc4[j].x += f * w.x; acc4[j].y += f * w.y;
            acc4[j].z += f * w.z; acc4[j].w += f * w.w;
        }
    }
    #pragma unroll
    for (int j = 0; j < 4; j++) {
        float4 o;
        o.x = fmaxf(acc4[j].x, 0.0f); o.y = fmaxf(acc4[j].y, 0.0f);
        o.z = fmaxf(acc4[j].z, 0.0f); o.w = fmaxf(acc4[j].w, 0.0f);
        *(float4*)&g_h[(size_t)b * HID + cb + j * 4] = o;
    }
}

// ---------------- aux loss ----------------
__global__ void k_aux(float* __restrict__ out, int out_size) {
    if (out_size <= B_ * D_ * HW) return;
    const float c0 = (float)g_counts[0], c1 = (float)g_counts[1];
    const float c2 = (float)g_counts[2], c3 = (float)g_counts[3];
    const float mean = (c0 + c1 + c2 + c3) * 0.25f;
    const float d0 = c0 - mean, d1 = c1 - mean, d2 = c2 - mean, d3 = c3 - mean;
    const float var = (d0 * d0 + d1 * d1 + d2 * d2 + d3 * d3) / 3.0f;
    const float cv2 = var / (mean * mean + 1e-10f);
    out[B_ * D_ * HW] = 2.0f * cv2 * 1e-2f;
}

// ---------------- expert GEMM, split-K, f32x2 ----------------
// grid (HID/BN2=16, B_/BM=4, E_*SPLITK=32), 256 threads
__global__ void k_gemm(const float* __restrict__ w2) {
    const int nt = blockIdx.x;
    const int mc = blockIdx.y;
    const int e  = blockIdx.z >> 3;
    const int kp = blockIdx.z & (SPLITK - 1);
    const int ce = g_counts[e];
    if (mc * BM >= ce) return;

    __shared__ float Ad[BK2][2 * BM + 4];   // duplicated A pairs (padded, 16B-aligned rows)
    __shared__ float Bs[BK2][BN2 + 4];
    __shared__ int   sbs[BM];

    const int t = threadIdx.x;
    if (t < BM) {
        const int m = mc * BM + t;
        sbs[t] = (m < ce) ? g_list[e * B_ + m] : -1;
    }
    __syncthreads();

    // A loader: thread t -> row ar (0..31), k-pair base ak (0,2,..,14)
    const int ar = t >> 3;
    const int ak = (t & 7) * 2;
    const int abb = sbs[ar];
    const float* aptr = &g_h[(size_t)((abb >= 0) ? abb : 0) * HID + kp * KR + ak];
    // B loader: thread t -> row br (0..15), chunk bc (0..15)
    const int br = t >> 4;
    const int bc = t & 15;
    const float* bptr = w2 + (size_t)e * HID * HID + (size_t)(kp * KR + br) * HID
                        + (size_t)nt * BN2 + bc * 4;
    // compute: rows ty*4.. (warp-uniform), cols tx*8..
    const int ty = t >> 5;
    const int tx = t & 31;

    u64 acc[4][4];
    #pragma unroll
    for (int r = 0; r < 4; r++)
        #pragma unroll
        for (int p = 0; p < 4; p++) acc[r][p] = 0ull;

    float2 pa;
    float4 pb0, pb1, pb2, pb3;

    // prologue loads (tile 0)
    pa  = *(const float2*)aptr;
    if (abb < 0) { pa.x = 0.0f; pa.y = 0.0f; }
    pb0 = *(const float4*)(bptr);
    pb1 = *(const float4*)(bptr + 64);
    pb2 = *(const float4*)(bptr + 128);
    pb3 = *(const float4*)(bptr + 192);

    for (int kt = 0; kt < NIT; kt++) {
        // regs -> smem
        {
            float2 d0; d0.x = pa.x; d0.y = pa.x;
            float2 d1; d1.x = pa.y; d1.y = pa.y;
            *(float2*)&Ad[ak][2 * ar]     = d0;
            *(float2*)&Ad[ak + 1][2 * ar] = d1;
            *(float4*)&Bs[br][bc * 4]       = pb0;
            *(float4*)&Bs[br][bc * 4 + 64]  = pb1;
            *(float4*)&Bs[br][bc * 4 + 128] = pb2;
            *(float4*)&Bs[br][bc * 4 + 192] = pb3;
        }
        __syncthreads();

        // prefetch next tile
        if (kt + 1 < NIT) {
            aptr += BK2;
            bptr += (size_t)BK2 * HID;
            pa  = *(const float2*)aptr;
            if (abb < 0) { pa.x = 0.0f; pa.y = 0.0f; }
            pb0 = *(const float4*)(bptr);
            pb1 = *(const float4*)(bptr + 64);
            pb2 = *(const float4*)(bptr + 128);
            pb3 = *(const float4*)(bptr + 192);
        }

        #pragma unroll
        for (int k = 0; k < BK2; k++) {
            const ulonglong2 a01 = *(const ulonglong2*)&Ad[k][ty * 8];      // (r0r0),(r1r1)
            const ulonglong2 a23 = *(const ulonglong2*)&Ad[k][ty * 8 + 4];  // (r2r2),(r3r3)
            const ulonglong2 b01 = *(const ulonglong2*)&Bs[k][tx * 8];      // (c0c1),(c2c3)
            const ulonglong2 b23 = *(const ulonglong2*)&Bs[k][tx * 8 + 4];  // (c4c5),(c6c7)
            ffma2(acc[0][0], a01.x, b01.x); ffma2(acc[0][1], a01.x, b01.y);
            ffma2(acc[0][2], a01.x, b23.x); ffma2(acc[0][3], a01.x, b23.y);
            ffma2(acc[1][0], a01.y, b01.x); ffma2(acc[1][1], a01.y, b01.y);
            ffma2(acc[1][2], a01.y, b23.x); ffma2(acc[1][3], a01.y, b23.y);
            ffma2(acc[2][0], a23.x, b01.x); ffma2(acc[2][1], a23.x, b01.y);
            ffma2(acc[2][2], a23.x, b23.x); ffma2(acc[2][3], a23.x, b23.y);
            ffma2(acc[3][0], a23.y, b01.x); ffma2(acc[3][1], a23.y, b01.y);
            ffma2(acc[3][2], a23.y, b23.x); ffma2(acc[3][3], a23.y, b23.y);
        }
        __syncthreads();
    }

    #pragma unroll
    for (int r = 0; r < 4; r++) {
        const int bb = sbs[ty * 4 + r];
        if (bb >= 0) {
            const int n = nt * BN2 + tx * 8;
            const float2 p0 = upk(acc[r][0]), p1 = upk(acc[r][1]);
            const float2 p2 = upk(acc[r][2]), p3 = upk(acc[r][3]);
            float4 o0; o0.x = p0.x; o0.y = p0.y; o0.z = p1.x; o0.w = p1.y;
            float4 o1; o1.x = p2.x; o1.y = p2.y; o1.z = p3.x; o1.w = p3.y;
            *(float4*)&g_part[kp][bb][n]     = o0;
            *(float4*)&g_part[kp][bb][n + 4] = o1;
        }
    }
}

// ---------------- partial-reduce + bias + softmax + transform + sigmoid ----------------
__global__ void k_softmax_apply(const float* __restrict__ in,
                                const float* __restrict__ b2,
                                float* __restrict__ out) {
    const int b = blockIdx.x;
    const int t = threadIdx.x;

    __shared__ float s_l[HID];
    __shared__ float s_y[64 * 65];
    __shared__ float s_in[D_ * 64];
    __shared__ float redm[8];
    __shared__ float reds[8];

    const int e = g_sel[b];
    const float* b2e = b2 + e * HID;
    #pragma unroll
    for (int u = 0; u < 16; u++) {
        const int idx = t + 256 * u;
        float v = b2e[idx];
        #pragma unroll
        for (int p = 0; p < SPLITK; p++) v += g_part[p][b][idx];
        s_l[idx] = v;
    }
    for (int i = t; i < D_ * 64; i += 256) s_in[i] = in[b * D_ * 64 + i];
    __syncthreads();

    float v = -1e30f;
    #pragma unroll
    for (int u = 0; u < 16; u++) v = fmaxf(v, s_l[t + 256 * u]);
    #pragma unroll
    for (int o = 16; o; o >>= 1) v = fmaxf(v, __shfl_xor_sync(0xffffffffu, v, o));
    if ((t & 31) == 0) redm[t >> 5] = v;
    __syncthreads();
    float mx = redm[0];
    #pragma unroll
    for (int i = 1; i < 8; i++) mx = fmaxf(mx, redm[i]);

    float s = 0.0f;
    #pragma unroll
    for (int u = 0; u < 16; u++) {
        const int idx = t + 256 * u;
        const float ev = expf(s_l[idx] - mx);
        s_l[idx] = ev;
        s += ev;
    }
    #pragma unroll
    for (int o = 16; o; o >>= 1) s += __shfl_xor_sync(0xffffffffu, s, o);
    if ((t & 31) == 0) reds[t >> 5] = s;
    __syncthreads();
    float tot = 0.0f;
    #pragma unroll
    for (int i = 0; i < 8; i++) tot += reds[i];
    const float inv = 1.0f / tot;

    #pragma unroll
    for (int u = 0; u < 16; u++) {
        const int idx = t + 256 * u;
        const int i = idx >> 6, j = idx & 63;
        s_y[j * 65 + i] = s_l[idx] * inv;
    }
    __syncthreads();

    for (int idx = t; idx < D_ * 64; idx += 256) {
        const int d = idx >> 6, i = idx & 63;
        float a = 0.0f;
        #pragma unroll
        for (int j = 0; j < 64; j++) a += s_y[j * 65 + i] * s_in[d * 64 + j];
        out[(b * D_ + d) * 64 + i] = 1.0f / (1.0f + expf(-a));
    }
}

// ---------------- launch ----------------
extern "C" void kernel_launch(void* const* d_in, const int* in_sizes, int n_in,
                              void* d_out, int out_size) {
    (void)in_sizes; (void)n_in;
    const float* in  = (const float*)d_in[0];
    const float* c1w = (const float*)d_in[1];
    const float* c1b = (const float*)d_in[2];
    const float* c2w = (const float*)d_in[3];
    const float* c2b = (const float*)d_in[4];
    const float* wg  = (const float*)d_in[5];
    const float* w1  = (const float*)d_in[6];
    const float* b1  = (const float*)d_in[7];
    const float* w2  = (const float*)d_in[8];
    const float* b2  = (const float*)d_in[9];
    float* out = (float*)d_out;

    k_reset<<<1, 32>>>();
    k1_conv_gate_h<<<B_, 256>>>(in, c1w, c1b, c2w, c2b, wg, w1, b1);
    k_aux<<<1, 1>>>(out, out_size);
    dim3 g3(HID / BN2, B_ / BM, E_ * SPLITK);
    k_gemm<<<g3, 256>>>(w2);
    k_softmax_apply<<<B_, 256>>>(in, b2, out);
}

// round 6
// speedup vs baseline: 1.9231x; 1.2386x over previous
#include <cuda_runtime.h>
#include <math.h>

#define B_     128
#define D_     20
#define HW     64
#define E_     4
#define HID    4096
#define IN_    64

#define SPLITK 16
#define KR     (HID / SPLITK)   // 256
#define BM     32
#define BN     256
#define BK     8
#define NIT    (KR / BK)        // 32

typedef unsigned long long u64;

// ---------------- device scratch ----------------
__device__ int   g_sel[B_];
__device__ int   g_counts[E_];
__device__ int   g_list[E_ * B_];
__device__ float g_h[(size_t)B_ * HID];
__device__ float g_part[SPLITK][B_][HID];   // 32MB split-K partials (L2-resident)

__device__ __forceinline__ void ffma2(u64 &d, u64 a, u64 b) {
    asm("fma.rn.f32x2 %0, %1, %2, %0;" : "+l"(d) : "l"(a), "l"(b));
}
__device__ __forceinline__ float2 upk(u64 v) {
    float2 r; asm("mov.b64 {%0,%1}, %2;" : "=f"(r.x), "=f"(r.y) : "l"(v)); return r;
}

// ---------------- reset ----------------
__global__ void k_reset() {
    if (threadIdx.x < E_) g_counts[threadIdx.x] = 0;
}

// ---------------- conv1 + conv2 + gating + h ----------------
__global__ void k1_conv_gate_h(const float* __restrict__ in,
                               const float* __restrict__ c1w,
                               const float* __restrict__ c1b,
                               const float* __restrict__ c2w,
                               const float* __restrict__ c2b,
                               const float* __restrict__ wg,
                               const float* __restrict__ w1,
                               const float* __restrict__ b1) {
    const int b = blockIdx.x;
    const int t = threadIdx.x;

    __shared__ float s_in[D_ * HW];
    __shared__ float s_pl[D_ * HW];
    __shared__ float s_c1w[272];
    __shared__ float s_c2w[1800];
    __shared__ float s_acc[4][HW];
    __shared__ float s_flat[IN_];
    __shared__ float s_log[E_];
    __shared__ int   s_sel;

    for (int i = t; i < D_ * HW; i += 256) s_in[i] = in[b * D_ * HW + i];
    for (int i = t; i < 270;      i += 256) s_c1w[i] = c1w[i];
    for (int i = t; i < 1800;     i += 256) s_c2w[i] = c2w[i];
    s_acc[t >> 6][t & 63] = 0.0f;
    __syncthreads();

    for (int ic = 0; ic < 10; ic++) {
        const float bias = c1b[ic];
        for (int idx = t; idx < D_ * HW; idx += 256) {
            const int d = idx >> 6, h = (idx >> 3) & 7, w = idx & 7;
            float a = bias;
            #pragma unroll
            for (int kd = 0; kd < 3; kd++) {
                const int dd = d + kd - 1;
                if ((unsigned)dd >= (unsigned)D_) continue;
                #pragma unroll
                for (int kh = 0; kh < 3; kh++) {
                    const int hh = h + kh - 1;
                    if ((unsigned)hh >= 8u) continue;
                    #pragma unroll
                    for (int kw = 0; kw < 3; kw++) {
                        const int ww = w + kw - 1;
                        if ((unsigned)ww >= 8u) continue;
                        a += s_in[dd * 64 + hh * 8 + ww] * s_c1w[ic * 27 + kd * 9 + kh * 3 + kw];
                    }
                }
            }
            s_pl[idx] = fmaxf(a, 0.0f);
        }
        __syncthreads();
        {
            const int part = t >> 6, hw = t & 63, h = hw >> 3, w = hw & 7;
            float a = 0.0f;
            for (int d = part * 5; d < part * 5 + 5; d++) {
                #pragma unroll
                for (int kh = 0; kh < 3; kh++) {
                    const int hh = h + kh - 1;
                    if ((unsigned)hh >= 8u) continue;
                    #pragma unroll
                    for (int kw = 0; kw < 3; kw++) {
                        const int ww = w + kw - 1;
                        if ((unsigned)ww >= 8u) continue;
                        a += s_pl[d * 64 + hh * 8 + ww] * s_c2w[(ic * 20 + d) * 9 + kh * 3 + kw];
                    }
                }
            }
            s_acc[part][hw] += a;
        }
        __syncthreads();
    }

    if (t < 64) {
        const float v = s_acc[0][t] + s_acc[1][t] + s_acc[2][t] + s_acc[3][t] + c2b[0];
        s_flat[t] = fmaxf(v, 0.0f);
    }
    __syncthreads();

    if (t < E_) {
        float a = 0.0f;
        for (int i = 0; i < 64; i++) a += s_flat[i] * wg[i * E_ + t];
        s_log[t] = a;
    }
    __syncthreads();
    if (t == 0) {
        int best = 0; float bv = s_log[0];
        #pragma unroll
        for (int e = 1; e < E_; e++) if (s_log[e] > bv) { bv = s_log[e]; best = e; }
        s_sel = best;
        g_sel[b] = best;
        const int pos = atomicAdd(&g_counts[best], 1);
        g_list[best * B_ + pos] = b;
    }
    __syncthreads();

    // h[b] = relu(flat @ w1[e] + b1[e]); thread t owns 16 contiguous cols t*16..
    const int e = s_sel;
    const int cb = t * 16;
    float4 acc4[4];
    #pragma unroll
    for (int j = 0; j < 4; j++) acc4[j] = *(const float4*)&b1[e * HID + cb + j * 4];
    const float* w1e = w1 + (size_t)e * IN_ * HID + cb;
    for (int i = 0; i < 64; i++) {
        const float f = s_flat[i];
        const float* row = w1e + (size_t)i * HID;
        #pragma unroll
        for (int j = 0; j < 4; j++) {
            const float4 w = *(const float4*)&row[j * 4];
            acc4[j].x += f * w.x; acc4[j].y += f * w.y;
            acc4[j].z += f * w.z; acc4[j].w += f * w.w;
        }
    }
    #pragma unroll
    for (int j = 0; j < 4; j++) {
        float4 o;
        o.x = fmaxf(acc4[j].x, 0.0f); o.y = fmaxf(acc4[j].y, 0.0f);
        o.z = fmaxf(acc4[j].z, 0.0f); o.w = fmaxf(acc4[j].w, 0.0f);
        *(float4*)&g_h[(size_t)b * HID + cb + j * 4] = o;
    }
}

// ---------------- aux loss ----------------
__global__ void k_aux(float* __restrict__ out, int out_size) {
    if (out_size <= B_ * D_ * HW) return;
    const float c0 = (float)g_counts[0], c1 = (float)g_counts[1];
    const float c2 = (float)g_counts[2], c3 = (float)g_counts[3];
    const float mean = (c0 + c1 + c2 + c3) * 0.25f;
    const float d0 = c0 - mean, d1 = c1 - mean, d2 = c2 - mean, d3 = c3 - mean;
    const float var = (d0 * d0 + d1 * d1 + d2 * d2 + d3 * d3) / 3.0f;
    const float cv2 = var / (mean * mean + 1e-10f);
    out[B_ * D_ * HW] = 2.0f * cv2 * 1e-2f;
}

// ---------------- expert GEMM, split-K, f32x2, 8x8 tiles ----------------
// grid (HID/BN=16, B_/BM=4, E_*SPLITK=64), 128 threads
// warp w owns rows w*8..w*8+7; lane owns cols {lane*4..+3, 128+lane*4..+3}
__global__ void __launch_bounds__(128) k_gemm(const float* __restrict__ w2) {
    const int nt = blockIdx.x;
    const int mc = blockIdx.y;
    const int e  = blockIdx.z >> 4;
    const int kp = blockIdx.z & (SPLITK - 1);
    const int ce = g_counts[e];
    if (mc * BM >= ce) return;

    __shared__ float Ad[BK][2 * BM + 4];   // duplicated A pairs, row = 272B (16B-aligned)
    __shared__ float Bs[BK][BN + 4];       // row = 1040B (16B-aligned)
    __shared__ int   sbs[BM];

    const int t = threadIdx.x;
    if (t < BM) {
        const int m = mc * BM + t;
        sbs[t] = (m < ce) ? g_list[e * B_ + m] : -1;
    }
    __syncthreads();

    // A loader: row ar (0..31), k-pair akq (0,2,4,6)
    const int ar  = t >> 2;
    const int akq = (t & 3) * 2;
    const int abb = sbs[ar];
    const float* aptr = &g_h[(size_t)((abb >= 0) ? abb : 0) * HID + kp * KR + akq];
    // B loader: row br (0..7), 16-col chunk bc (0..15)
    const int br = t >> 4;
    const int bc = t & 15;
    const float* bptr = w2 + (size_t)e * HID * HID + (size_t)(kp * KR + br) * HID
                        + (size_t)nt * BN + bc * 16;
    // compute mapping
    const int wid  = t >> 5;   // row group: rows wid*8..+7
    const int lane = t & 31;   // cols lane*4..+3 and 128+lane*4..+3

    u64 acc[8][4];
    #pragma unroll
    for (int r = 0; r < 8; r++)
        #pragma unroll
        for (int p = 0; p < 4; p++) acc[r][p] = 0ull;

    float2 pa;
    float4 pb0, pb1, pb2, pb3;

    pa  = *(const float2*)aptr;
    if (abb < 0) { pa.x = 0.0f; pa.y = 0.0f; }
    pb0 = *(const float4*)(bptr);
    pb1 = *(const float4*)(bptr + 4);
    pb2 = *(const float4*)(bptr + 8);
    pb3 = *(const float4*)(bptr + 12);

    for (int kt = 0; kt < NIT; kt++) {
        {
            float2 d0; d0.x = pa.x; d0.y = pa.x;
            float2 d1; d1.x = pa.y; d1.y = pa.y;
            *(float2*)&Ad[akq][2 * ar]     = d0;
            *(float2*)&Ad[akq + 1][2 * ar] = d1;
            *(float4*)&Bs[br][bc * 16]      = pb0;
            *(float4*)&Bs[br][bc * 16 + 4]  = pb1;
            *(float4*)&Bs[br][bc * 16 + 8]  = pb2;
            *(float4*)&Bs[br][bc * 16 + 12] = pb3;
        }
        __syncthreads();

        if (kt + 1 < NIT) {
            aptr += BK;
            bptr += (size_t)BK * HID;
            pa  = *(const float2*)aptr;
            if (abb < 0) { pa.x = 0.0f; pa.y = 0.0f; }
            pb0 = *(const float4*)(bptr);
            pb1 = *(const float4*)(bptr + 4);
            pb2 = *(const float4*)(bptr + 8);
            pb3 = *(const float4*)(bptr + 12);
        }

        #pragma unroll
        for (int k = 0; k < BK; k++) {
            // A: 8 rows duplicated -> 4 x 16B broadcast loads
            const ulonglong2 a01 = *(const ulonglong2*)&Ad[k][wid * 16];       // rows 0,1
            const ulonglong2 a23 = *(const ulonglong2*)&Ad[k][wid * 16 + 4];   // rows 2,3
            const ulonglong2 a45 = *(const ulonglong2*)&Ad[k][wid * 16 + 8];   // rows 4,5
            const ulonglong2 a67 = *(const ulonglong2*)&Ad[k][wid * 16 + 12];  // rows 6,7
            // B: two conflict-free 16B loads (phase-contiguous 128B blocks)
            const ulonglong2 b0 = *(const ulonglong2*)&Bs[k][lane * 4];        // cols c0..c3
            const ulonglong2 b1 = *(const ulonglong2*)&Bs[k][128 + lane * 4];  // cols c128..c131
            ffma2(acc[0][0], a01.x, b0.x); ffma2(acc[0][1], a01.x, b0.y);
            ffma2(acc[0][2], a01.x, b1.x); ffma2(acc[0][3], a01.x, b1.y);
            ffma2(acc[1][0], a01.y, b0.x); ffma2(acc[1][1], a01.y, b0.y);
            ffma2(acc[1][2], a01.y, b1.x); ffma2(acc[1][3], a01.y, b1.y);
            ffma2(acc[2][0], a23.x, b0.x); ffma2(acc[2][1], a23.x, b0.y);
            ffma2(acc[2][2], a23.x, b1.x); ffma2(acc[2][3], a23.x, b1.y);
            ffma2(acc[3][0], a23.y, b0.x); ffma2(acc[3][1], a23.y, b0.y);
            ffma2(acc[3][2], a23.y, b1.x); ffma2(acc[3][3], a23.y, b1.y);
            ffma2(acc[4][0], a45.x, b0.x); ffma2(acc[4][1], a45.x, b0.y);
            ffma2(acc[4][2], a45.x, b1.x); ffma2(acc[4][3], a45.x, b1.y);
            ffma2(acc[5][0], a45.y, b0.x); ffma2(acc[5][1], a45.y, b0.y);
            ffma2(acc[5][2], a45.y, b1.x); ffma2(acc[5][3], a45.y, b1.y);
            ffma2(acc[6][0], a67.x, b0.x); ffma2(acc[6][1], a67.x, b0.y);
            ffma2(acc[6][2], a67.x, b1.x); ffma2(acc[6][3], a67.x, b1.y);
            ffma2(acc[7][0], a67.y, b0.x); ffma2(acc[7][1], a67.y, b0.y);
            ffma2(acc[7][2], a67.y, b1.x); ffma2(acc[7][3], a67.y, b1.y);
        }
        __syncthreads();
    }

    #pragma unroll
    for (int r = 0; r < 8; r++) {
        const int bb = sbs[wid * 8 + r];
        if (bb >= 0) {
            const int n = nt * BN + lane * 4;
            const float2 p0 = upk(acc[r][0]), p1 = upk(acc[r][1]);
            const float2 p2 = upk(acc[r][2]), p3 = upk(acc[r][3]);
            float4 o0; o0.x = p0.x; o0.y = p0.y; o0.z = p1.x; o0.w = p1.y;
            float4 o1; o1.x = p2.x; o1.y = p2.y; o1.z = p3.x; o1.w = p3.y;
            *(float4*)&g_part[kp][bb][n]       = o0;
            *(float4*)&g_part[kp][bb][n + 128] = o1;
        }
    }
}

// ---------------- partial-reduce + bias + softmax + transform + sigmoid ----------------
__global__ void k_softmax_apply(const float* __restrict__ in,
                                const float* __restrict__ b2,
                                float* __restrict__ out) {
    const int b = blockIdx.x;
    const int t = threadIdx.x;

    __shared__ float s_l[HID];
    __shared__ float s_y[64 * 65];
    __shared__ float s_in[D_ * 64];
    __shared__ float redm[8];
    __shared__ float reds[8];

    const int e = g_sel[b];
    const float* b2e = b2 + e * HID;
    #pragma unroll
    for (int u = 0; u < 16; u++) {
        const int idx = t + 256 * u;
        float v = b2e[idx];
        #pragma unroll
        for (int p = 0; p < SPLITK; p++) v += g_part[p][b][idx];
        s_l[idx] = v;
    }
    for (int i = t; i < D_ * 64; i += 256) s_in[i] = in[b * D_ * 64 + i];
    __syncthreads();

    float v = -1e30f;
    #pragma unroll
    for (int u = 0; u < 16; u++) v = fmaxf(v, s_l[t + 256 * u]);
    #pragma unroll
    for (int o = 16; o; o >>= 1) v = fmaxf(v, __shfl_xor_sync(0xffffffffu, v, o));
    if ((t & 31) == 0) redm[t >> 5] = v;
    __syncthreads();
    float mx = redm[0];
    #pragma unroll
    for (int i = 1; i < 8; i++) mx = fmaxf(mx, redm[i]);

    float s = 0.0f;
    #pragma unroll
    for (int u = 0; u < 16; u++) {
        const int idx = t + 256 * u;
        const float ev = expf(s_l[idx] - mx);
        s_l[idx] = ev;
        s += ev;
    }
    #pragma unroll
    for (int o = 16; o; o >>= 1) s += __shfl_xor_sync(0xffffffffu, s, o);
    if ((t & 31) == 0) reds[t >> 5] = s;
    __syncthreads();
    float tot = 0.0f;
    #pragma unroll
    for (int i = 0; i < 8; i++) tot += reds[i];
    const float inv = 1.0f / tot;

    #pragma unroll
    for (int u = 0; u < 16; u++) {
        const int idx = t + 256 * u;
        const int i = idx >> 6, j = idx & 63;
        s_y[j * 65 + i] = s_l[idx] * inv;
    }
    __syncthreads();

    for (int idx = t; idx < D_ * 64; idx += 256) {
        const int d = idx >> 6, i = idx & 63;
        float a = 0.0f;
        #pragma unroll
        for (int j = 0; j < 64; j++) a += s_y[j * 65 + i] * s_in[d * 64 + j];
        out[(b * D_ + d) * 64 + i] = 1.0f / (1.0f + expf(-a));
    }
}

// ---------------- launch ----------------
extern "C" void kernel_launch(void* const* d_in, const int* in_sizes, int n_in,
                              void* d_out, int out_size) {
    (void)in_sizes; (void)n_in;
    const float* in  = (const float*)d_in[0];
    const float* c1w = (const float*)d_in[1];
    const float* c1b = (const float*)d_in[2];
    const float* c2w = (const float*)d_in[3];
    const float* c2b = (const float*)d_in[4];
    const float* wg  = (const float*)d_in[5];
    const float* w1  = (const float*)d_in[6];
    const float* b1  = (const float*)d_in[7];
    const float* w2  = (const float*)d_in[8];
    const float* b2  = (const float*)d_in[9];
    float* out = (float*)d_out;

    k_reset<<<1, 32>>>();
    k1_conv_gate_h<<<B_, 256>>>(in, c1w, c1b, c2w, c2b, wg, w1, b1);
    k_aux<<<1, 1>>>(out, out_size);
    dim3 g3(HID / BN, B_ / BM, E_ * SPLITK);
    k_gemm<<<g3, 128>>>(w2);
    k_softmax_apply<<<B_, 256>>>(in, b2, out);
}